// round 3
// baseline (speedup 1.0000x reference)
#include <cuda_runtime.h>
#include <cstdint>

// Shapes (fixed by the benchmark)
#define B 4
#define L 2048
#define H 8
#define D 64
#define SK 40          // sample_k
#define U 40           // top-k queries kept
#define BH (B*H)       // 32
#define C (H*D)        // 512 columns for cumsum view

// Stage-1 tiling
#define QT 256         // queries per tile
#define NQT (L/QT)     // 8
#define KC 128         // keys per chunk
#define NKC (L/KC)     // 16
#define BCAP 1024      // bucket capacity (mean 640, sd 24.5 -> +15 sigma)
#define PQ 68          // smem pitch (floats) for Q/K tiles

// Attention chunking
#define KCH 128
#define NCHK (L/KCH)   // 16
#define PKS 68
#define PVS 66

// Cumsum chunking
#define NCH 64
#define CHUNK (L/NCH)  // 32

// -------- scratch (device globals; no allocation allowed) --------
__device__ unsigned g_bkt[NQT * NKC * BCAP];
__device__ int      g_bcnt[NQT * NKC];
__device__ float    g_S[(size_t)BH * L * SK];   // sampled scores
__device__ float    g_M[BH * L];
__device__ int      g_Mtop[BH * U];
__device__ float    g_pm[BH * U * NCHK];
__device__ float    g_pl[BH * U * NCHK];
__device__ float    g_pacc[BH * U * NCHK * D];
__device__ float    g_csum[B * NCH * C];

// ===================== Stage 1a: bucket the sample indices =====================
// idx is shared across (b,h). Entry pack: q_local[8b]<<13 | s[6b]<<7 | k_local[7b].
__global__ void k_bucket(const int* __restrict__ idx)
{
    __shared__ int scnt[NKC];
    int tile = blockIdx.x, t = threadIdx.x;
    if (t < NKC) scnt[t] = 0;
    __syncthreads();
    for (int i = t; i < QT * SK; i += 256) {
        int q = i / SK, s = i % SK;
        int ki = idx[(tile * QT + q) * SK + s];
        int c = ki >> 7, kl = ki & 127;
        int slot = atomicAdd(&scnt[c], 1);
        if (slot < BCAP)
            g_bkt[(tile * NKC + c) * BCAP + slot] =
                (unsigned)((q << 13) | (s << 7) | kl);
    }
    __syncthreads();
    if (t < NKC) g_bcnt[tile * NKC + t] = min(scnt[t], BCAP);
}

// ===================== Stage 1b: tiled sampled dots -> g_S =====================
// Block = (bh, query-tile). Q tile resident in smem; K streamed chunk-by-chunk.
// 8-lane groups compute one dot each (identical arithmetic to prior kernel).
__global__ void __launch_bounds__(256) k_gather(const float* __restrict__ Q,
                                                const float* __restrict__ K)
{
    __shared__ float Qs[QT * PQ];
    __shared__ float Kc[KC * PQ];
    __shared__ int scnt[NKC];

    int blk = blockIdx.x;
    int bh = blk >> 3, tile = blk & 7;
    int b = bh >> 3, h = bh & 7;
    int t = threadIdx.x;

    if (t < NKC) scnt[t] = g_bcnt[tile * NKC + t];
    // Q tile: QT rows x 64 floats (float4 loads, pitched store)
    for (int i = t; i < QT * 16; i += 256) {
        int r = i >> 4, dd = (i & 15) << 2;
        *(float4*)&Qs[r * PQ + dd] =
            *(const float4*)&Q[(((size_t)b * L + tile * QT + r) * H + h) * D + dd];
    }

    int grp = t >> 3, j = t & 7;

    for (int c = 0; c < NKC; c++) {
        __syncthreads();   // prior chunk fully consumed (and Qs ready on c==0)
        for (int i = t; i < KC * 16; i += 256) {
            int r = i >> 4, dd = (i & 15) << 2;
            *(float4*)&Kc[r * PQ + dd] =
                *(const float4*)&K[(((size_t)b * L + c * KC + r) * H + h) * D + dd];
        }
        __syncthreads();

        int cnt = scnt[c];
        int iters = (cnt + 31) >> 5;
        const unsigned* bk = &g_bkt[(tile * NKC + c) * BCAP];
        for (int it = 0; it < iters; it++) {
            int e = it * 32 + grp;
            bool act = e < cnt;
            unsigned pk = act ? bk[e] : 0u;
            int q = pk >> 13, s = (pk >> 7) & 63, kl = pk & 127;
            const float* qp = &Qs[q * PQ + j * 8];
            const float* kp = &Kc[kl * PQ + j * 8];
            float4 qa = *(const float4*)qp;
            float4 qb = *(const float4*)(qp + 4);
            float4 ka = *(const float4*)kp;
            float4 kb = *(const float4*)(kp + 4);
            float d = qa.x * ka.x + qa.y * ka.y + qa.z * ka.z + qa.w * ka.w
                    + qb.x * kb.x + qb.y * kb.y + qb.z * kb.z + qb.w * kb.w;
            d += __shfl_xor_sync(0xffffffffu, d, 1);
            d += __shfl_xor_sync(0xffffffffu, d, 2);
            d += __shfl_xor_sync(0xffffffffu, d, 4);
            if (act && j == 0)
                g_S[((size_t)bh * L + tile * QT + q) * SK + s] = d;
        }
    }
}

// ===================== Stage 1c: M = max_s - mean_s (exact s-order) ===========
__global__ void k_M()
{
    int gid = blockIdx.x * 256 + threadIdx.x;   // bh*L + q
    const float* row = &g_S[(size_t)gid * SK];
    float mx = -1e30f, sm = 0.f;
    #pragma unroll
    for (int s = 0; s < SK; s++) {
        float v = row[s];
        mx = fmaxf(mx, v);
        sm += v;
    }
    g_M[gid] = mx - sm * (1.0f / SK);
}

// ===================== Stage 2: top-U per (b,h) =====================
// Iterative argmax, ties -> lowest index (matches jax.lax.top_k).
__global__ void k_topk()
{
    __shared__ float sv[L];
    __shared__ float wv[8];
    __shared__ int   wi[8];
    int bh = blockIdx.x;
    int t = threadIdx.x;
    int w = t >> 5, lane = t & 31;

    for (int i = t; i < L; i += 256) sv[i] = g_M[bh * L + i];
    __syncthreads();

    for (int r = 0; r < U; r++) {
        float bv = -1e38f; int bi = L;
        #pragma unroll
        for (int k = 0; k < 8; k++) {
            int i = t + k * 256;        // increasing -> strict > keeps lowest i
            float v = sv[i];
            if (v > bv) { bv = v; bi = i; }
        }
        #pragma unroll
        for (int o = 16; o; o >>= 1) {
            float v2 = __shfl_xor_sync(0xffffffffu, bv, o);
            int   i2 = __shfl_xor_sync(0xffffffffu, bi, o);
            if (v2 > bv || (v2 == bv && i2 < bi)) { bv = v2; bi = i2; }
        }
        if (lane == 0) { wv[w] = bv; wi[w] = bi; }
        __syncthreads();
        if (t == 0) {
            float fv = wv[0]; int fi = wi[0];
            #pragma unroll
            for (int k = 1; k < 8; k++)
                if (wv[k] > fv || (wv[k] == fv && wi[k] < fi)) { fv = wv[k]; fi = wi[k]; }
            g_Mtop[bh * U + r] = fi;
            sv[fi] = -1e38f;
        }
        __syncthreads();
    }
}

// ===================== Stage 3: cumsum of V along L -> out =====================
__global__ void k_cumsum_a(const float* __restrict__ V)
{
    int blk = blockIdx.x;
    int b = blk / NCH, ch = blk % NCH;
    int c = threadIdx.x;
    const float* base = V + ((size_t)b * L + ch * CHUNK) * C + c;
    float s = 0.f;
    #pragma unroll
    for (int l = 0; l < CHUNK; l++) s += base[(size_t)l * C];
    g_csum[((size_t)b * NCH + ch) * C + c] = s;
}

__global__ void k_cumsum_c(const float* __restrict__ V, float* __restrict__ out)
{
    int blk = blockIdx.x;
    int b = blk / NCH, ch = blk % NCH;
    int c = threadIdx.x;
    float run = 0.f;
    for (int j = 0; j < ch; j++)
        run += g_csum[((size_t)b * NCH + j) * C + c];
    const float* vb = V   + ((size_t)b * L + ch * CHUNK) * C + c;
    float*       ob = out + ((size_t)b * L + ch * CHUNK) * C + c;
    #pragma unroll
    for (int l0 = 0; l0 < CHUNK; l0 += 8) {
        float v[8];
        #pragma unroll
        for (int j = 0; j < 8; j++) v[j] = vb[(size_t)(l0 + j) * C];
        #pragma unroll
        for (int j = 0; j < 8; j++) {
            run += v[j];
            ob[(size_t)(l0 + j) * C] = run;
        }
    }
}

// ===================== Stage 4: dense attention partials =====================
__global__ void __launch_bounds__(256) k_attn_partial(
    const float* __restrict__ Q,
    const float* __restrict__ K,
    const float* __restrict__ V)
{
    extern __shared__ float smf[];
    float* Ks = smf;                       // KCH * PKS
    float* Vs = Ks + KCH * PKS;            // KCH * PVS
    float* Qs = Vs + KCH * PVS;            // U * D
    float* pb = Qs + U * D;                // 8 warps * 5 q * 128 k
    int*   ps = (int*)(pb + 8 * 5 * KCH);  // U

    int bh = blockIdx.x >> 4;
    int ch = blockIdx.x & 15;
    int b = bh >> 3, h = bh & 7;
    int t = threadIdx.x;
    int k0 = ch * KCH;

    for (int i = t; i < KCH * D; i += 256) {
        int r = i >> 6, d = i & 63;
        size_t gidx = (((size_t)b * L + (k0 + r)) * H + h) * D + d;
        Ks[r * PKS + d] = K[gidx];
        Vs[r * PVS + d] = V[gidx];
    }
    if (t < U) ps[t] = g_Mtop[bh * U + t];
    __syncthreads();
    for (int i = t; i < U * D; i += 256) {
        int u = i >> 6, d = i & 63;
        Qs[i] = Q[(((size_t)b * L + ps[u]) * H + h) * D + d];
    }
    __syncthreads();

    int w = t >> 5, lane = t & 31;
    const float4* Qb = (const float4*)Qs;

    float s4[5][4];
    #pragma unroll
    for (int q = 0; q < 5; q++)
        #pragma unroll
        for (int g = 0; g < 4; g++) s4[q][g] = 0.f;

    #pragma unroll 4
    for (int i = 0; i < 16; i++) {
        float4 kk[4];
        #pragma unroll
        for (int g = 0; g < 4; g++)
            kk[g] = *(const float4*)&Ks[(g * 32 + lane) * PKS + 4 * i];
        #pragma unroll
        for (int q = 0; q < 5; q++) {
            float4 qv = Qb[(w * 5 + q) * 16 + i];
            #pragma unroll
            for (int g = 0; g < 4; g++)
                s4[q][g] += qv.x * kk[g].x + qv.y * kk[g].y
                          + qv.z * kk[g].z + qv.w * kk[g].w;
        }
    }

    #pragma unroll
    for (int q = 0; q < 5; q++) {
        int u = w * 5 + q;
        int p = ps[u];
        float sc[4]; bool ok[4];
        float m = -1e30f;
        #pragma unroll
        for (int g = 0; g < 4; g++) {
            sc[g] = s4[q][g] * 0.125f;
            ok[g] = (k0 + g * 32 + lane) <= p;
            m = fmaxf(m, ok[g] ? sc[g] : -1e30f);
        }
        #pragma unroll
        for (int o = 16; o; o >>= 1)
            m = fmaxf(m, __shfl_xor_sync(0xffffffffu, m, o));
        float l = 0.f;
        #pragma unroll
        for (int g = 0; g < 4; g++) {
            float pv = ok[g] ? __expf(sc[g] - m) : 0.f;
            l += pv;
            pb[w * (5 * KCH) + q * KCH + g * 32 + lane] = pv;
        }
        #pragma unroll
        for (int o = 16; o; o >>= 1)
            l += __shfl_xor_sync(0xffffffffu, l, o);
        if (lane == 0) {
            int pi = (bh * U + u) * NCHK + ch;
            g_pm[pi] = m;
            g_pl[pi] = l;
        }
    }
    __syncwarp();

    float2 acc[5];
    #pragma unroll
    for (int q = 0; q < 5; q++) acc[q] = make_float2(0.f, 0.f);

    #pragma unroll 4
    for (int k = 0; k < KCH; k += 4) {
        float2 v0 = *(const float2*)&Vs[(k + 0) * PVS + 2 * lane];
        float2 v1 = *(const float2*)&Vs[(k + 1) * PVS + 2 * lane];
        float2 v2 = *(const float2*)&Vs[(k + 2) * PVS + 2 * lane];
        float2 v3 = *(const float2*)&Vs[(k + 3) * PVS + 2 * lane];
        #pragma unroll
        for (int q = 0; q < 5; q++) {
            float4 pq = *(const float4*)&pb[w * (5 * KCH) + q * KCH + k];
            acc[q].x += pq.x * v0.x + pq.y * v1.x + pq.z * v2.x + pq.w * v3.x;
            acc[q].y += pq.x * v0.y + pq.y * v1.y + pq.z * v2.y + pq.w * v3.y;
        }
    }

    #pragma unroll
    for (int q = 0; q < 5; q++) {
        int u = w * 5 + q;
        int pi = (bh * U + u) * NCHK + ch;
        *(float2*)&g_pacc[(size_t)pi * D + 2 * lane] = acc[q];
    }
}

// ===================== Stage 5: combine partials, scatter rows =====================
__global__ void k_attn_reduce(float* __restrict__ out)
{
    int task = blockIdx.x * (blockDim.x >> 5) + (threadIdx.x >> 5);
    if (task >= BH * U) return;
    int lane = threadIdx.x & 31;
    int bh = task / U, u = task % U;
    int b = bh >> 3, h = bh & 7;

    float m = -1e30f;
    #pragma unroll
    for (int c = 0; c < NCHK; c++) m = fmaxf(m, g_pm[task * NCHK + c]);
    float Lsum = 0.f;
    float2 a = make_float2(0.f, 0.f);
    #pragma unroll
    for (int c = 0; c < NCHK; c++) {
        float wgt = __expf(g_pm[task * NCHK + c] - m);
        Lsum += g_pl[task * NCHK + c] * wgt;
        float2 pa = *(const float2*)&g_pacc[(size_t)(task * NCHK + c) * D + 2 * lane];
        a.x += pa.x * wgt;
        a.y += pa.y * wgt;
    }
    float inv = 1.0f / Lsum;
    int p = g_Mtop[bh * U + u];
    size_t o = (((size_t)b * L + p) * H + h) * D + 2 * lane;
    out[o + 0] = a.x * inv;
    out[o + 1] = a.y * inv;
}

// ===================== launch =====================
extern "C" void kernel_launch(void* const* d_in, const int* in_sizes, int n_in,
                              void* d_out, int out_size)
{
    const float* Q   = (const float*)d_in[0];
    const float* K   = (const float*)d_in[1];
    const float* V   = (const float*)d_in[2];
    const int*   idx = (const int*)d_in[3];
    float* out = (float*)d_out;

    const int smem_k4 = (KCH * PKS + KCH * PVS + U * D + 8 * 5 * KCH) * (int)sizeof(float)
                      + U * (int)sizeof(int);
    cudaFuncSetAttribute(k_attn_partial, cudaFuncAttributeMaxDynamicSharedMemorySize, smem_k4);

    // Stage 1: buckets -> tiled sampled dots -> M
    k_bucket<<<NQT, 256>>>(idx);
    k_gather<<<BH * NQT, 256>>>(Q, K);
    k_M<<<BH * L / 256, 256>>>();
    // Stage 2: top-k
    k_topk<<<BH, 256>>>();
    // Stage 3: cumsum -> out
    k_cumsum_a<<<B * NCH, C>>>(V);
    k_cumsum_c<<<B * NCH, C>>>(V, out);
    // Stage 4: dense attention partials for top queries
    k_attn_partial<<<BH * NCHK, 256, smem_k4>>>(Q, K, V);
    // Stage 5: combine + scatter
    k_attn_reduce<<<(BH * U) / 8, 256>>>(out);
}

// round 4
// speedup vs baseline: 2.2021x; 2.2021x over previous
#include <cuda_runtime.h>
#include <cstdint>

// Shapes (fixed by the benchmark)
#define B 4
#define L 2048
#define H 8
#define D 64
#define SK 40          // sample_k
#define U 40           // top-k queries kept
#define BH (B*H)       // 32
#define C (H*D)        // 512 columns for cumsum view

// Attention chunking
#define KCH 128        // keys per chunk in dense attention
#define NCHK (L/KCH)   // 16
#define PKS 68         // Ks pitch (floats): conflict-free float4 key-major reads
#define PVS 66         // Vs pitch (floats): conflict-free float2 d-major reads

// Cumsum chunking
#define NCH 64
#define CHUNK (L/NCH)  // 32

// -------- scratch (device globals; no allocation allowed) --------
__device__ float g_M[BH * L];
__device__ int   g_Mtop[BH * U];
__device__ float g_pm[BH * U * NCHK];
__device__ float g_pl[BH * U * NCHK];
__device__ float g_pacc[BH * U * NCHK * D];
__device__ float g_csum[B * NCH * C];

// ===================== Stage 1: sampled scores -> M =====================
// Block per query q (2048 blocks, 256 threads). Thread t: b=t>>6, h=(t>>3)&7,
// dim-group g=t&7 (8 floats). Q row cached in registers; each sample is one
// fully coalesced 2KB gather of K[b, ki, :, :]; 8-lane butterfly reduce.
// Samples processed in batches of 4: 8 LDG.128 issued before any reduction.
__global__ void __launch_bounds__(256) k_sample_scores(
    const float* __restrict__ Q,
    const float* __restrict__ K,
    const int*   __restrict__ idx)
{
    __shared__ int sidx[SK];
    int q = blockIdx.x;
    int t = threadIdx.x;
    int b = t >> 6;
    int h = (t >> 3) & 7;
    int g = t & 7;

    if (t < SK) sidx[t] = idx[q * SK + t];
    __syncthreads();

    const float* qp = Q + (((size_t)b * L + q) * H + h) * D + g * 8;
    float4 qa = *(const float4*)qp;
    float4 qb = *(const float4*)(qp + 4);

    float mx = -1e30f, sm = 0.f;
    const size_t hoff = (size_t)h * D + (size_t)g * 8;
    const float* Kb = K + (size_t)b * L * (H * D) + hoff;

    #pragma unroll
    for (int s0 = 0; s0 < SK; s0 += 4) {
        float4 ka[4], kb[4];
        #pragma unroll
        for (int j = 0; j < 4; j++) {
            const float* kp = Kb + (size_t)sidx[s0 + j] * (H * D);
            ka[j] = *(const float4*)kp;
            kb[j] = *(const float4*)(kp + 4);
        }
        #pragma unroll
        for (int j = 0; j < 4; j++) {
            float d = qa.x * ka[j].x + qa.y * ka[j].y + qa.z * ka[j].z + qa.w * ka[j].w
                    + qb.x * kb[j].x + qb.y * kb[j].y + qb.z * kb[j].z + qb.w * kb[j].w;
            d += __shfl_xor_sync(0xffffffffu, d, 1);
            d += __shfl_xor_sync(0xffffffffu, d, 2);
            d += __shfl_xor_sync(0xffffffffu, d, 4);
            mx = fmaxf(mx, d);
            sm += d;
        }
    }
    if (g == 0)
        g_M[(t >> 3) * L + q] = mx - sm * (1.0f / SK);
}

// ===================== Stage 2: top-U per (b,h) =====================
// 1024 threads, 2 elems each; shuffle-only argmax per round.
// Ties -> lowest index (matches jax.lax.top_k).
__global__ void __launch_bounds__(1024) k_topk()
{
    __shared__ float sv[L];
    __shared__ float wv[32];
    __shared__ int   wi[32];
    int bh = blockIdx.x;
    int t = threadIdx.x;
    int w = t >> 5, lane = t & 31;

    sv[t] = g_M[bh * L + t];
    sv[t + 1024] = g_M[bh * L + t + 1024];
    __syncthreads();

    for (int r = 0; r < U; r++) {
        float v0 = sv[t], v1 = sv[t + 1024];
        float bv; int bi;
        if (v0 >= v1) { bv = v0; bi = t; }           // tie -> lower index
        else          { bv = v1; bi = t + 1024; }
        #pragma unroll
        for (int o = 16; o; o >>= 1) {
            float v2 = __shfl_xor_sync(0xffffffffu, bv, o);
            int   i2 = __shfl_xor_sync(0xffffffffu, bi, o);
            if (v2 > bv || (v2 == bv && i2 < bi)) { bv = v2; bi = i2; }
        }
        if (lane == 0) { wv[w] = bv; wi[w] = bi; }
        __syncthreads();
        if (w == 0) {
            bv = wv[lane]; bi = wi[lane];
            #pragma unroll
            for (int o = 16; o; o >>= 1) {
                float v2 = __shfl_xor_sync(0xffffffffu, bv, o);
                int   i2 = __shfl_xor_sync(0xffffffffu, bi, o);
                if (v2 > bv || (v2 == bv && i2 < bi)) { bv = v2; bi = i2; }
            }
            if (lane == 0) {
                g_Mtop[bh * U + r] = bi;
                sv[bi] = -1e38f;
            }
        }
        __syncthreads();
    }
}

// ===================== Stage 3: cumsum of V along L -> out =====================
// View V/out as [B][L][C], C = 512. Pass A: chunk sums. Pass C: each block
// computes its own prefix from the (L2-resident) chunk sums, then scans.
__global__ void k_cumsum_a(const float* __restrict__ V)
{
    int blk = blockIdx.x;          // 0 .. B*NCH-1
    int b = blk / NCH, ch = blk % NCH;
    int c = threadIdx.x;           // 512
    const float* base = V + ((size_t)b * L + ch * CHUNK) * C + c;
    float s = 0.f;
    #pragma unroll
    for (int l = 0; l < CHUNK; l++) s += base[(size_t)l * C];
    g_csum[((size_t)b * NCH + ch) * C + c] = s;
}

__global__ void k_cumsum_c(const float* __restrict__ V, float* __restrict__ out)
{
    int blk = blockIdx.x;
    int b = blk / NCH, ch = blk % NCH;
    int c = threadIdx.x;
    float run = 0.f;
    for (int j = 0; j < ch; j++)
        run += g_csum[((size_t)b * NCH + j) * C + c];
    const float* vb = V   + ((size_t)b * L + ch * CHUNK) * C + c;
    float*       ob = out + ((size_t)b * L + ch * CHUNK) * C + c;
    #pragma unroll
    for (int l0 = 0; l0 < CHUNK; l0 += 8) {
        float v[8];
        #pragma unroll
        for (int j = 0; j < 8; j++) v[j] = vb[(size_t)(l0 + j) * C];
        #pragma unroll
        for (int j = 0; j < 8; j++) {
            run += v[j];
            ob[(size_t)(l0 + j) * C] = run;
        }
    }
}

// ===================== Stage 4: dense attention partials =====================
// Block = (b,h, key-chunk). 8 warps; each warp owns 5 of the 40 queries.
// Scores: K float4 shared across the warp's 5 queries, scores in registers.
// Whole 128-key chunk softmaxed at once (no online rescale inside chunk).
// AV: V float2 shared across the 5 queries via smem-staged p (broadcast reads).
__global__ void __launch_bounds__(256) k_attn_partial(
    const float* __restrict__ Q,
    const float* __restrict__ K,
    const float* __restrict__ V)
{
    extern __shared__ float smf[];
    float* Ks = smf;                       // KCH * PKS
    float* Vs = Ks + KCH * PKS;            // KCH * PVS
    float* Qs = Vs + KCH * PVS;            // U * D
    float* pb = Qs + U * D;                // 8 warps * 5 q * 128 k
    int*   ps = (int*)(pb + 8 * 5 * KCH);  // U

    int bh = blockIdx.x >> 4;
    int ch = blockIdx.x & 15;
    int b = bh >> 3, h = bh & 7;
    int t = threadIdx.x;
    int k0 = ch * KCH;

    // Load K,V chunk (global coalesced along d; STS consecutive -> conflict-free)
    for (int i = t; i < KCH * D; i += 256) {
        int r = i >> 6, d = i & 63;
        size_t gidx = (((size_t)b * L + (k0 + r)) * H + h) * D + d;
        Ks[r * PKS + d] = K[gidx];
        Vs[r * PVS + d] = V[gidx];
    }
    if (t < U) ps[t] = g_Mtop[bh * U + t];
    __syncthreads();
    for (int i = t; i < U * D; i += 256) {
        int u = i >> 6, d = i & 63;
        Qs[i] = Q[(((size_t)b * L + ps[u]) * H + h) * D + d];
    }
    __syncthreads();

    int w = t >> 5, lane = t & 31;
    const float4* Qb = (const float4*)Qs;

    // ---- scores: lane covers keys {g*32+lane : g<4}; 5 q accumulators each ----
    float s4[5][4];
    #pragma unroll
    for (int q = 0; q < 5; q++)
        #pragma unroll
        for (int g = 0; g < 4; g++) s4[q][g] = 0.f;

    #pragma unroll 4
    for (int i = 0; i < 16; i++) {
        float4 kk[4];
        #pragma unroll
        for (int g = 0; g < 4; g++)
            kk[g] = *(const float4*)&Ks[(g * 32 + lane) * PKS + 4 * i];
        #pragma unroll
        for (int q = 0; q < 5; q++) {
            float4 qv = Qb[(w * 5 + q) * 16 + i];
            #pragma unroll
            for (int g = 0; g < 4; g++)
                s4[q][g] += qv.x * kk[g].x + qv.y * kk[g].y
                          + qv.z * kk[g].z + qv.w * kk[g].w;
        }
    }

    // ---- per-q softmax over the 128-key chunk; stage p in smem ----
    #pragma unroll
    for (int q = 0; q < 5; q++) {
        int u = w * 5 + q;
        int p = ps[u];
        float sc[4]; bool ok[4];
        float m = -1e30f;
        #pragma unroll
        for (int g = 0; g < 4; g++) {
            sc[g] = s4[q][g] * 0.125f;             // 1/sqrt(64)
            ok[g] = (k0 + g * 32 + lane) <= p;
            m = fmaxf(m, ok[g] ? sc[g] : -1e30f);
        }
        #pragma unroll
        for (int o = 16; o; o >>= 1)
            m = fmaxf(m, __shfl_xor_sync(0xffffffffu, m, o));
        float l = 0.f;
        #pragma unroll
        for (int g = 0; g < 4; g++) {
            float pv = ok[g] ? __expf(sc[g] - m) : 0.f;
            l += pv;
            pb[w * (5 * KCH) + q * KCH + g * 32 + lane] = pv;
        }
        #pragma unroll
        for (int o = 16; o; o >>= 1)
            l += __shfl_xor_sync(0xffffffffu, l, o);
        if (lane == 0) {
            int pi = (bh * U + u) * NCHK + ch;
            g_pm[pi] = m;
            g_pl[pi] = l;
        }
    }
    __syncwarp();

    // ---- AV: lane owns dims {2*lane, 2*lane+1}; V shared across 5 queries ----
    float2 acc[5];
    #pragma unroll
    for (int q = 0; q < 5; q++) acc[q] = make_float2(0.f, 0.f);

    #pragma unroll 4
    for (int k = 0; k < KCH; k += 4) {
        float2 v0 = *(const float2*)&Vs[(k + 0) * PVS + 2 * lane];
        float2 v1 = *(const float2*)&Vs[(k + 1) * PVS + 2 * lane];
        float2 v2 = *(const float2*)&Vs[(k + 2) * PVS + 2 * lane];
        float2 v3 = *(const float2*)&Vs[(k + 3) * PVS + 2 * lane];
        #pragma unroll
        for (int q = 0; q < 5; q++) {
            float4 pq = *(const float4*)&pb[w * (5 * KCH) + q * KCH + k];
            acc[q].x += pq.x * v0.x + pq.y * v1.x + pq.z * v2.x + pq.w * v3.x;
            acc[q].y += pq.x * v0.y + pq.y * v1.y + pq.z * v2.y + pq.w * v3.y;
        }
    }

    #pragma unroll
    for (int q = 0; q < 5; q++) {
        int u = w * 5 + q;
        int pi = (bh * U + u) * NCHK + ch;
        *(float2*)&g_pacc[(size_t)pi * D + 2 * lane] = acc[q];
    }
}

// ===================== Stage 5: combine partials, scatter rows =====================
__global__ void k_attn_reduce(float* __restrict__ out)
{
    int task = blockIdx.x * (blockDim.x >> 5) + (threadIdx.x >> 5);
    if (task >= BH * U) return;
    int lane = threadIdx.x & 31;
    int bh = task / U, u = task % U;
    int b = bh >> 3, h = bh & 7;

    float m = -1e30f;
    #pragma unroll
    for (int c = 0; c < NCHK; c++) m = fmaxf(m, g_pm[task * NCHK + c]);
    float Lsum = 0.f;
    float2 a = make_float2(0.f, 0.f);
    #pragma unroll
    for (int c = 0; c < NCHK; c++) {
        float wgt = __expf(g_pm[task * NCHK + c] - m);
        Lsum += g_pl[task * NCHK + c] * wgt;
        float2 pa = *(const float2*)&g_pacc[(size_t)(task * NCHK + c) * D + 2 * lane];
        a.x += pa.x * wgt;
        a.y += pa.y * wgt;
    }
    float inv = 1.0f / Lsum;
    int p = g_Mtop[bh * U + u];
    size_t o = (((size_t)b * L + p) * H + h) * D + 2 * lane;
    out[o + 0] = a.x * inv;
    out[o + 1] = a.y * inv;
}

// ===================== launch =====================
extern "C" void kernel_launch(void* const* d_in, const int* in_sizes, int n_in,
                              void* d_out, int out_size)
{
    const float* Q   = (const float*)d_in[0];
    const float* K   = (const float*)d_in[1];
    const float* V   = (const float*)d_in[2];
    const int*   idx = (const int*)d_in[3];
    float* out = (float*)d_out;

    const int smem_k4 = (KCH * PKS + KCH * PVS + U * D + 8 * 5 * KCH) * (int)sizeof(float)
                      + U * (int)sizeof(int);
    cudaFuncSetAttribute(k_attn_partial, cudaFuncAttributeMaxDynamicSharedMemorySize, smem_k4);

    // Stage 1: M scores (block per query)
    k_sample_scores<<<L, 256>>>(Q, K, idx);
    // Stage 2: top-k
    k_topk<<<BH, 1024>>>();
    // Stage 3: cumsum -> out
    k_cumsum_a<<<B * NCH, C>>>(V);
    k_cumsum_c<<<B * NCH, C>>>(V, out);
    // Stage 4: dense attention partials for top queries
    k_attn_partial<<<BH * NCHK, 256, smem_k4>>>(Q, K, V);
    // Stage 5: combine + scatter
    k_attn_reduce<<<(BH * U) / 8, 256>>>(out);
}